// round 9
// baseline (speedup 1.0000x reference)
#include <cuda_runtime.h>
#include <cuda_bf16.h>
#include <cuda_fp16.h>
#include <math.h>
#include <stdint.h>

#define B_    2
#define NB_   512
#define L_    64
#define H_    8
#define DH_   64
#define C_    512
#define C3_   1536
#define MROWS 65536          // B*NB*L
#define BNB   1024           // B*NB
#define NBLL  2097152        // NB*L*L

// ---------------- static scratch (no allocations allowed) ----------------
__device__ __half g_qkvh [100663296]; // [MROWS][1536] fp16
__device__ float g_gate  [16777216];   // [H][NB][L][L]
__device__ float g_smask [2097152];    // [NB][L][L]   bias3 + (mask?0:-1e30)
__device__ float g_gblock[524288];     // [MROWS][H]
__device__ float g_vblock[524288];     // [BNB][512]
__device__ float g_bnode [524288];     // [BNB][512]
__device__ __half g_xq[33554432];      // x fp16 [MROWS][512]
__device__ __half g_mq[33554432];      // xmid fp16
__device__ __half g_wq[786432];        // w_qkv^T fp16 [1536][512]
__device__ __half g_wp[262144];        // w_proj^T fp16 [512][512]

// =================== PTX helpers (baseline ISA only: sm_80+) ===================
__device__ __forceinline__ uint32_t s2u(const void* p) {
    return (uint32_t)__cvta_generic_to_shared(p);
}
__device__ __forceinline__ void cp16(uint32_t dst, const void* src) {
    asm volatile("cp.async.cg.shared.global [%0], [%1], 16;" :: "r"(dst), "l"(src));
}
#define LDSM4(r, a) \
    asm volatile("ldmatrix.sync.aligned.m8n8.x4.shared.b16 {%0,%1,%2,%3}, [%4];" \
        : "=r"((r)[0]), "=r"((r)[1]), "=r"((r)[2]), "=r"((r)[3]) : "r"(a))
#define MMA16816H(c, a, b) \
    asm volatile("mma.sync.aligned.m16n8k16.row.col.f32.f16.f16.f32 " \
        "{%0,%1,%2,%3}, {%4,%5,%6,%7}, {%8,%9}, {%0,%1,%2,%3};" \
        : "+f"((c)[0]), "+f"((c)[1]), "+f"((c)[2]), "+f"((c)[3]) \
        : "r"((a)[0]), "r"((a)[1]), "r"((a)[2]), "r"((a)[3]), "r"((b)[0]), "r"((b)[1]))

// =================== fp16 single-pass GEMM via HMMA mma.sync ===================
// CTA 128(M) x 256(N), 512 threads (16 warps 4Mx4N), warp tile 32x64.
// K chunks of 64, double buffered. Output fp32 (Cf) or fp16 (Ch).
#define A_TILE 16384
#define B_TILE 32768
#define STAGE_BYTES 49152
#define GSMEM (2 * STAGE_BYTES)

__device__ __forceinline__ void gemm_load_stage(
    uint32_t st, int tid, int kc,
    const __half* __restrict__ A, const __half* __restrict__ Bm)
{
    #pragma unroll
    for (int r = 0; r < 2; r++) {
        int idx = r * 512 + tid;
        int row = idx >> 3, ch = idx & 7;
        uint32_t d = row * 128 + ((ch ^ (row & 7)) << 4);
        cp16(st + d, A + (size_t)row * 512 + kc * 64 + ch * 8);
    }
    #pragma unroll
    for (int r = 0; r < 4; r++) {
        int idx = r * 512 + tid;
        int row = idx >> 3, ch = idx & 7;
        uint32_t d = row * 128 + ((ch ^ (row & 7)) << 4);
        cp16(st + A_TILE + d, Bm + (size_t)row * 512 + kc * 64 + ch * 8);
    }
    asm volatile("cp.async.commit_group;" ::: "memory");
}

__global__ void __launch_bounds__(512, 1)
gemm_fp16_kernel(const __half* __restrict__ A, const __half* __restrict__ Bm,
                 const float* __restrict__ bias, float* __restrict__ Cf,
                 __half* __restrict__ Ch, int ldC)
{
    extern __shared__ __align__(1024) char smem[];
    uint32_t sb = s2u(smem);
    int tid = threadIdx.x;
    int warp = tid >> 5, lane = tid & 31;
    int m0 = blockIdx.y * 128, n0 = blockIdx.x * 256;
    int wm = (warp & 3) * 32, wn = (warp >> 2) * 64;

    const __half* pA = A + (size_t)m0 * 512;
    const __half* pB = Bm + (size_t)n0 * 512;

    float acc[2][8][4];
    #pragma unroll
    for (int i = 0; i < 2; i++)
        #pragma unroll
        for (int j = 0; j < 8; j++)
            #pragma unroll
            for (int t = 0; t < 4; t++) acc[i][j][t] = 0.f;

    int aRow[2], bRow[4];
    #pragma unroll
    for (int mi = 0; mi < 2; mi++) aRow[mi] = wm + mi * 16 + (lane & 15);
    #pragma unroll
    for (int nj = 0; nj < 4; nj++) bRow[nj] = wn + nj * 16 + (lane & 7) + ((lane >> 4) << 3);
    int aSel = lane >> 4;
    int bSel = (lane >> 3) & 1;

    gemm_load_stage(sb, tid, 0, pA, pB);

    for (int kc = 0; kc < 8; kc++) {
        if (kc + 1 < 8) {
            gemm_load_stage(sb + ((kc + 1) & 1) * STAGE_BYTES, tid, kc + 1, pA, pB);
            asm volatile("cp.async.wait_group 1;" ::: "memory");
        } else {
            asm volatile("cp.async.wait_group 0;" ::: "memory");
        }
        __syncthreads();

        uint32_t stA = sb + (kc & 1) * STAGE_BYTES;
        uint32_t stB = stA + A_TILE;

        #pragma unroll
        for (int kk = 0; kk < 4; kk++) {
            uint32_t af[2][4];
            int chA = kk * 2 + aSel;
            #pragma unroll
            for (int mi = 0; mi < 2; mi++) {
                uint32_t ad = aRow[mi] * 128 + ((chA ^ (aRow[mi] & 7)) << 4);
                LDSM4(af[mi], stA + ad);
            }
            int chB = kk * 2 + bSel;
            #pragma unroll
            for (int nj = 0; nj < 4; nj++) {
                uint32_t bf[4];
                uint32_t bd = bRow[nj] * 128 + ((chB ^ (bRow[nj] & 7)) << 4);
                LDSM4(bf, stB + bd);
                #pragma unroll
                for (int mi = 0; mi < 2; mi++) {
                    MMA16816H(acc[mi][nj * 2 + 0], af[mi], (bf + 0));
                    MMA16816H(acc[mi][nj * 2 + 1], af[mi], (bf + 2));
                }
            }
        }
        __syncthreads();
    }

    // epilogue: +bias; fp32 or fp16 store
    #pragma unroll
    for (int mi = 0; mi < 2; mi++) {
        int row = m0 + wm + mi * 16 + (lane >> 2);
        #pragma unroll
        for (int ni = 0; ni < 8; ni++) {
            int col = n0 + wn + ni * 8 + (lane & 3) * 2;
            float2 bv = *(const float2*)(bias + col);
            float v00 = acc[mi][ni][0] + bv.x, v01 = acc[mi][ni][1] + bv.y;
            float v10 = acc[mi][ni][2] + bv.x, v11 = acc[mi][ni][3] + bv.y;
            if (Cf) {
                float2 o0 = {v00, v01}, o1 = {v10, v11};
                *(float2*)(Cf + (size_t)row * ldC + col) = o0;
                *(float2*)(Cf + (size_t)(row + 8) * ldC + col) = o1;
            } else {
                *(__half2*)(Ch + (size_t)row * ldC + col) = __floats2half2_rn(v00, v01);
                *(__half2*)(Ch + (size_t)(row + 8) * ldC + col) = __floats2half2_rn(v10, v11);
            }
        }
    }
}

// ============ convert x -> fp16, fused g_block sigmoid ============
__global__ void __launch_bounds__(256) convx_kernel(const float* __restrict__ x,
    const float* __restrict__ wblk, const float* __restrict__ bblk)
{
    __shared__ __align__(16) float swt[8][512];   // wblk transposed
    int tid = threadIdx.x;
    for (int idx = tid; idx < 4096; idx += 256)
        swt[idx & 7][idx >> 3] = wblk[idx];
    __syncthreads();
    int wid = tid >> 5, lane = tid & 31;
    int row = blockIdx.x * 8 + wid;
    const float* xr = x + (size_t)row * 512;
    float acc[8] = {};
    #pragma unroll
    for (int i = 0; i < 4; i++) {
        int c = i * 128 + lane * 4;
        float4 v = *(const float4*)(xr + c);
        __half2 h0 = __floats2half2_rn(v.x, v.y);
        __half2 h1 = __floats2half2_rn(v.z, v.w);
        size_t o = (size_t)row * 512 + c;
        *(__half2*)(g_xq + o) = h0; *(__half2*)(g_xq + o + 2) = h1;
        #pragma unroll
        for (int h = 0; h < 8; h++) {
            float4 wv = *(const float4*)(&swt[h][c]);
            acc[h] += v.x * wv.x + v.y * wv.y + v.z * wv.z + v.w * wv.w;
        }
    }
    #pragma unroll
    for (int m = 16; m; m >>= 1)
        #pragma unroll
        for (int h = 0; h < 8; h++) acc[h] += __shfl_xor_sync(0xffffffffu, acc[h], m);
    if (lane == 0) {
        #pragma unroll
        for (int h = 0; h < 8; h++)
            g_gblock[row * 8 + h] = 1.f / (1.f + __expf(-(acc[h] + bblk[h])));
    }
}

// ============ weight transpose + fp16: W[K][N] -> T[N][K] ============
__global__ void wsplit_kernel(const float* __restrict__ W,
    __half* __restrict__ T, int Kd, int Nd)
{
    __shared__ float tile[32][33];
    int tx = threadIdx.x & 31, ty = threadIdx.x >> 5;
    int n0 = blockIdx.x * 32, k0 = blockIdx.y * 32;
    #pragma unroll
    for (int r = 0; r < 4; r++)
        tile[ty + r * 8][tx] = W[(size_t)(k0 + ty + r * 8) * Nd + n0 + tx];
    __syncthreads();
    #pragma unroll
    for (int r = 0; r < 4; r++) {
        int n = ty + r * 8;
        T[(size_t)(n0 + n) * Kd + k0 + tx] = __float2half_rn(tile[tx][n]);
    }
}

// ================= prep: fixed mask, bias diag, gate MLP =================
__global__ void prep_kernel(const int* __restrict__ mask,
                            const float* __restrict__ ef,
                            const float* __restrict__ w1, const float* __restrict__ b1,
                            const float* __restrict__ w2, const float* __restrict__ b2)
{
    __shared__ float sw1[64], sb1[16], sw2[128], sb2[8];
    __shared__ int ssum;
    int t   = threadIdx.x;          // k index
    int nbq = blockIdx.x;           // nb*64+q
    int q   = nbq & 63;
    sw1[t] = w1[t];
    sw2[t] = w2[t]; sw2[t + 64] = w2[t + 64];
    if (t < 16) sb1[t] = b1[t];
    if (t < 8)  sb2[t] = b2[t];
    if (t == 0) ssum = 0;
    __syncthreads();
    int m = mask[nbq * 64 + t];
    atomicAdd(&ssum, m);
    __syncthreads();
    int mf = m;
    if (q == t && ssum == 0) mf = 1;

    float e0, e1, e2, e3;
    if (q == t) { e0 = e1 = e2 = 0.f; e3 = 1.f; }
    else {
        const float* p = ef + ((size_t)nbq * 64 + t) * 4;
        e0 = p[0]; e1 = p[1]; e2 = p[2]; e3 = p[3];
    }
    float hb[16];
    #pragma unroll
    for (int i = 0; i < 16; i++) {
        float s = sb1[i] + e0 * sw1[i] + e1 * sw1[16 + i] + e2 * sw1[32 + i] + e3 * sw1[48 + i];
        hb[i] = 0.5f * s * (1.f + erff(s * 0.70710678118654752f));
    }
    #pragma unroll
    for (int h = 0; h < 8; h++) {
        float s = sb2[h];
        #pragma unroll
        for (int i = 0; i < 16; i++) s += hb[i] * sw2[i * 8 + h];
        g_gate[h * NBLL + nbq * 64 + t] = mf ? s : 0.f;
    }
    g_smask[nbq * 64 + t] = e3 + (mf ? 0.f : -1e30f);
}

// ================= block mean =================
__global__ void bnode_kernel(const float* __restrict__ x)
{
    int bn = blockIdx.x, c = threadIdx.x;   // 512 threads
    const float* p = x + (size_t)bn * 64 * 512 + c;
    float s = 0.f;
    #pragma unroll 8
    for (int l = 0; l < 64; l++) s += p[l * 512];
    g_bnode[bn * 512 + c] = s * (1.f / 64.f);
}

// ================= v_block = bnode @ w_qkv[:,2C:] + b =================
__global__ void vblock_kernel(const float* __restrict__ wqkv, const float* __restrict__ bqkv)
{
    __shared__ float sA[16][512];
    int t = threadIdx.x;                 // 512
    int r0 = blockIdx.x * 16;
    for (int r = 0; r < 16; r++) sA[r][t] = g_bnode[(r0 + r) * 512 + t];
    __syncthreads();
    float acc[16];
    #pragma unroll
    for (int r = 0; r < 16; r++) acc[r] = 0.f;
    for (int k = 0; k < 512; k++) {
        float w = wqkv[(size_t)k * 1536 + 1024 + t];
        #pragma unroll
        for (int r = 0; r < 16; r++) acc[r] += sA[r][k] * w;
    }
    float bb = bqkv[1024 + t];
    #pragma unroll
    for (int r = 0; r < 16; r++) g_vblock[(r0 + r) * 512 + t] = acc[r] + bb;
}

// ================= attention per (b,nb,h) =================
__device__ __forceinline__ int swz(int row, int col) {
    return row * 64 + ((((col >> 2) ^ (row & 15)) << 2) | (col & 3));
}
__device__ __forceinline__ int swz4(int row, int c4) {
    return row * 64 + (((c4) ^ (row & 15)) << 2);
}

__global__ void __launch_bounds__(256) attn_kernel()
{
    __shared__ __align__(16) float qT[64 * 64];
    __shared__ __align__(16) float kT[64 * 64];
    __shared__ __align__(16) float vs[64 * 64];
    int tid = threadIdx.x;
    int cid = blockIdx.x;
    int h  = cid & 7;
    int bn = cid >> 3;
    int nb = bn & 511;
    int rbase = bn * 64;

    // load q/k/v (fp16, 8 elems per 16B) -> fp32 swizzled smem
    #pragma unroll
    for (int p = 0; p < 2; p++) {
        int idx = p * 256 + tid;       // 0..511
        int l = idx >> 3, d8 = (idx & 7) * 8;
        const __half* base = g_qkvh + (size_t)(rbase + l) * 1536 + h * 64 + d8;
        uint4 qv = *(const uint4*)(base);
        uint4 kv = *(const uint4*)(base + 512);
        uint4 vv = *(const uint4*)(base + 1024);
        const __half2* qh = (const __half2*)&qv;
        const __half2* kh = (const __half2*)&kv;
        const __half2* vh = (const __half2*)&vv;
        #pragma unroll
        for (int j = 0; j < 4; j++) {
            float2 qf = __half22float2(qh[j]);
            float2 kf = __half22float2(kh[j]);
            float2 vf = __half22float2(vh[j]);
            int d = d8 + j * 2;
            qT[swz(d, l)]     = qf.x; qT[swz(d + 1, l)] = qf.y;
            kT[swz(d, l)]     = kf.x; kT[swz(d + 1, l)] = kf.y;
            vs[l * 64 + d]     = vf.x; vs[l * 64 + d + 1] = vf.y;
        }
    }
    __syncthreads();

    int tq = tid >> 4, tk = tid & 15;
    int qi0 = tq * 4, ki0 = tk * 4;

    float acc[4][4] = {};
    #pragma unroll 8
    for (int d = 0; d < 64; d++) {
        float4 a = *(const float4*)(&qT[swz4(d, tq)]);
        float4 b = *(const float4*)(&kT[swz4(d, tk)]);
        float ar[4] = {a.x, a.y, a.z, a.w};
        float br[4] = {b.x, b.y, b.z, b.w};
        #pragma unroll
        for (int i = 0; i < 4; i++)
            #pragma unroll
            for (int j = 0; j < 4; j++)
                acc[i][j] += ar[i] * br[j];
    }

    const float* smp = g_smask + nb * 4096;
    #pragma unroll
    for (int i = 0; i < 4; i++) {
        int qrow = qi0 + i;
        float s[4];
        #pragma unroll
        for (int j = 0; j < 4; j++)
            s[j] = acc[i][j] * 0.125f + smp[qrow * 64 + ki0 + j];
        float mx = fmaxf(fmaxf(s[0], s[1]), fmaxf(s[2], s[3]));
        #pragma unroll
        for (int m = 8; m; m >>= 1) mx = fmaxf(mx, __shfl_xor_sync(0xffffffffu, mx, m, 16));
        float sum = 0.f;
        #pragma unroll
        for (int j = 0; j < 4; j++) { s[j] = __expf(s[j] - mx); sum += s[j]; }
        #pragma unroll
        for (int m = 8; m; m >>= 1) sum += __shfl_xor_sync(0xffffffffu, sum, m, 16);
        float inv = 1.f / sum;
        const float* gp = g_gate + h * NBLL + nb * 4096 + qrow * 64 + ki0;
        #pragma unroll
        for (int j = 0; j < 4; j++) acc[i][j] = s[j] * inv + gp[j];
    }
    __syncthreads();
    float* ss = qT;
    #pragma unroll
    for (int i = 0; i < 4; i++)
        #pragma unroll
        for (int j = 0; j < 4; j++)
            ss[swz(ki0 + j, qi0 + i)] = acc[i][j];
    __syncthreads();

    float o[4][4] = {};
    int dj0 = tk * 4;
    #pragma unroll 8
    for (int k = 0; k < 64; k++) {
        float4 a = *(const float4*)(&ss[swz4(k, tq)]);
        float4 b = *(const float4*)(&vs[k * 64 + dj0]);
        float ar[4] = {a.x, a.y, a.z, a.w};
        float br[4] = {b.x, b.y, b.z, b.w};
        #pragma unroll
        for (int i = 0; i < 4; i++)
            #pragma unroll
            for (int j = 0; j < 4; j++)
                o[i][j] += ar[i] * br[j];
    }

    float4 vb = *(const float4*)(g_vblock + bn * 512 + h * 64 + dj0);
    #pragma unroll
    for (int i = 0; i < 4; i++) {
        int row = rbase + qi0 + i;
        float gb = g_gblock[row * 8 + h];
        __half2 h0 = __floats2half2_rn(o[i][0] + gb * vb.x, o[i][1] + gb * vb.y);
        __half2 h1 = __floats2half2_rn(o[i][2] + gb * vb.z, o[i][3] + gb * vb.w);
        size_t ofs = (size_t)row * 512 + h * 64 + dj0;
        *(__half2*)(g_mq + ofs) = h0; *(__half2*)(g_mq + ofs + 2) = h1;
    }
}

// ================= launch =================
extern "C" void kernel_launch(void* const* d_in, const int* in_sizes, int n_in,
                              void* d_out, int out_size)
{
    const float* x       = (const float*)d_in[0];
    const int*   amask   = (const int*)  d_in[1];
    const float* edge    = (const float*)d_in[2];
    const float* w_qkv   = (const float*)d_in[3];
    const float* b_qkv   = (const float*)d_in[4];
    const float* w_proj  = (const float*)d_in[5];
    const float* b_proj  = (const float*)d_in[6];
    const float* w_eg1   = (const float*)d_in[7];
    const float* b_eg1   = (const float*)d_in[8];
    const float* w_eg2   = (const float*)d_in[9];
    const float* b_eg2   = (const float*)d_in[10];
    const float* w_blk   = (const float*)d_in[11];
    const float* b_blk   = (const float*)d_in[12];
    float* out = (float*)d_out;

    void *qkvh, *xq, *mq, *wq, *wp;
    cudaGetSymbolAddress(&qkvh, g_qkvh);
    cudaGetSymbolAddress(&xq, g_xq);
    cudaGetSymbolAddress(&mq, g_mq);
    cudaGetSymbolAddress(&wq, g_wq);
    cudaGetSymbolAddress(&wp, g_wp);

    cudaFuncSetAttribute(gemm_fp16_kernel,
                         cudaFuncAttributeMaxDynamicSharedMemorySize, GSMEM);

    convx_kernel<<<MROWS / 8, 256>>>(x, w_blk, b_blk);
    wsplit_kernel<<<dim3(48, 16), 256>>>(w_qkv, (__half*)wq, 512, 1536);
    wsplit_kernel<<<dim3(16, 16), 256>>>(w_proj, (__half*)wp, 512, 512);
    prep_kernel  <<<NB_ * 64, 64>>>(amask, edge, w_eg1, b_eg1, w_eg2, b_eg2);
    bnode_kernel <<<BNB, 512>>>(x);
    vblock_kernel<<<64, 512>>>(w_qkv, b_qkv);

    gemm_fp16_kernel<<<dim3(6, 512), 512, GSMEM>>>(
        (const __half*)xq, (const __half*)wq, b_qkv,
        nullptr, (__half*)qkvh, 1536);

    attn_kernel<<<BNB * H_, 256>>>();

    gemm_fp16_kernel<<<dim3(2, 512), 512, GSMEM>>>(
        (const __half*)mq, (const __half*)wp, b_proj,
        out, nullptr, 512);
}

// round 10
// speedup vs baseline: 1.3148x; 1.3148x over previous
#include <cuda_runtime.h>
#include <cuda_bf16.h>
#include <cuda_fp16.h>
#include <math.h>
#include <stdint.h>

#define B_    2
#define NB_   512
#define L_    64
#define H_    8
#define DH_   64
#define C_    512
#define C3_   1536
#define MROWS 65536          // B*NB*L
#define BNB   1024           // B*NB
#define NBLL  2097152        // NB*L*L

// ---------------- static scratch (no allocations allowed) ----------------
__device__ __half g_qkvh [100663296]; // [MROWS][1536] fp16
__device__ __half g_gateh[16777216];   // [H][NB][L][L] fp16
__device__ float g_smask [2097152];    // [NB][L][L]   bias3 + (mask?0:-1e30)
__device__ float g_gblock[524288];     // [MROWS][H]
__device__ float g_vblock[524288];     // [BNB][512]
__device__ float g_bnode [524288];     // [BNB][512]
__device__ __half g_xq[33554432];      // x fp16 [MROWS][512]
__device__ __half g_mq[33554432];      // xmid fp16
__device__ __half g_wq[786432];        // w_qkv^T fp16 [1536][512]
__device__ __half g_wp[262144];        // w_proj^T fp16 [512][512]

// =================== PTX helpers (baseline ISA only: sm_80+) ===================
__device__ __forceinline__ uint32_t s2u(const void* p) {
    return (uint32_t)__cvta_generic_to_shared(p);
}
__device__ __forceinline__ void cp16(uint32_t dst, const void* src) {
    asm volatile("cp.async.cg.shared.global [%0], [%1], 16;" :: "r"(dst), "l"(src));
}
#define LDSM4(r, a) \
    asm volatile("ldmatrix.sync.aligned.m8n8.x4.shared.b16 {%0,%1,%2,%3}, [%4];" \
        : "=r"((r)[0]), "=r"((r)[1]), "=r"((r)[2]), "=r"((r)[3]) : "r"(a))
#define LDSM4T(r, a) \
    asm volatile("ldmatrix.sync.aligned.m8n8.x4.trans.shared.b16 {%0,%1,%2,%3}, [%4];" \
        : "=r"((r)[0]), "=r"((r)[1]), "=r"((r)[2]), "=r"((r)[3]) : "r"(a))
#define MMA16816H(c, a, b) \
    asm volatile("mma.sync.aligned.m16n8k16.row.col.f32.f16.f16.f32 " \
        "{%0,%1,%2,%3}, {%4,%5,%6,%7}, {%8,%9}, {%0,%1,%2,%3};" \
        : "+f"((c)[0]), "+f"((c)[1]), "+f"((c)[2]), "+f"((c)[3]) \
        : "r"((a)[0]), "r"((a)[1]), "r"((a)[2]), "r"((a)[3]), "r"((b)[0]), "r"((b)[1]))

// =================== fp16 single-pass GEMM via HMMA mma.sync ===================
// CTA 128(M) x 256(N), 512 threads (16 warps 4Mx4N), warp tile 32x64.
// K chunks of 64, double buffered. Output fp32 (Cf) or fp16 (Ch).
#define A_TILE 16384
#define B_TILE 32768
#define STAGE_BYTES 49152
#define GSMEM (2 * STAGE_BYTES)

__device__ __forceinline__ void gemm_load_stage(
    uint32_t st, int tid, int kc,
    const __half* __restrict__ A, const __half* __restrict__ Bm)
{
    #pragma unroll
    for (int r = 0; r < 2; r++) {
        int idx = r * 512 + tid;
        int row = idx >> 3, ch = idx & 7;
        uint32_t d = row * 128 + ((ch ^ (row & 7)) << 4);
        cp16(st + d, A + (size_t)row * 512 + kc * 64 + ch * 8);
    }
    #pragma unroll
    for (int r = 0; r < 4; r++) {
        int idx = r * 512 + tid;
        int row = idx >> 3, ch = idx & 7;
        uint32_t d = row * 128 + ((ch ^ (row & 7)) << 4);
        cp16(st + A_TILE + d, Bm + (size_t)row * 512 + kc * 64 + ch * 8);
    }
    asm volatile("cp.async.commit_group;" ::: "memory");
}

__global__ void __launch_bounds__(512, 1)
gemm_fp16_kernel(const __half* __restrict__ A, const __half* __restrict__ Bm,
                 const float* __restrict__ bias, float* __restrict__ Cf,
                 __half* __restrict__ Ch, int ldC)
{
    extern __shared__ __align__(1024) char smem[];
    uint32_t sb = s2u(smem);
    int tid = threadIdx.x;
    int warp = tid >> 5, lane = tid & 31;
    int m0 = blockIdx.y * 128, n0 = blockIdx.x * 256;
    int wm = (warp & 3) * 32, wn = (warp >> 2) * 64;

    const __half* pA = A + (size_t)m0 * 512;
    const __half* pB = Bm + (size_t)n0 * 512;

    float acc[2][8][4];
    #pragma unroll
    for (int i = 0; i < 2; i++)
        #pragma unroll
        for (int j = 0; j < 8; j++)
            #pragma unroll
            for (int t = 0; t < 4; t++) acc[i][j][t] = 0.f;

    int aRow[2], bRow[4];
    #pragma unroll
    for (int mi = 0; mi < 2; mi++) aRow[mi] = wm + mi * 16 + (lane & 15);
    #pragma unroll
    for (int nj = 0; nj < 4; nj++) bRow[nj] = wn + nj * 16 + (lane & 7) + ((lane >> 4) << 3);
    int aSel = lane >> 4;
    int bSel = (lane >> 3) & 1;

    gemm_load_stage(sb, tid, 0, pA, pB);

    for (int kc = 0; kc < 8; kc++) {
        if (kc + 1 < 8) {
            gemm_load_stage(sb + ((kc + 1) & 1) * STAGE_BYTES, tid, kc + 1, pA, pB);
            asm volatile("cp.async.wait_group 1;" ::: "memory");
        } else {
            asm volatile("cp.async.wait_group 0;" ::: "memory");
        }
        __syncthreads();

        uint32_t stA = sb + (kc & 1) * STAGE_BYTES;
        uint32_t stB = stA + A_TILE;

        #pragma unroll
        for (int kk = 0; kk < 4; kk++) {
            uint32_t af[2][4];
            int chA = kk * 2 + aSel;
            #pragma unroll
            for (int mi = 0; mi < 2; mi++) {
                uint32_t ad = aRow[mi] * 128 + ((chA ^ (aRow[mi] & 7)) << 4);
                LDSM4(af[mi], stA + ad);
            }
            int chB = kk * 2 + bSel;
            #pragma unroll
            for (int nj = 0; nj < 4; nj++) {
                uint32_t bf[4];
                uint32_t bd = bRow[nj] * 128 + ((chB ^ (bRow[nj] & 7)) << 4);
                LDSM4(bf, stB + bd);
                #pragma unroll
                for (int mi = 0; mi < 2; mi++) {
                    MMA16816H(acc[mi][nj * 2 + 0], af[mi], (bf + 0));
                    MMA16816H(acc[mi][nj * 2 + 1], af[mi], (bf + 2));
                }
            }
        }
        __syncthreads();
    }

    #pragma unroll
    for (int mi = 0; mi < 2; mi++) {
        int row = m0 + wm + mi * 16 + (lane >> 2);
        #pragma unroll
        for (int ni = 0; ni < 8; ni++) {
            int col = n0 + wn + ni * 8 + (lane & 3) * 2;
            float2 bv = *(const float2*)(bias + col);
            float v00 = acc[mi][ni][0] + bv.x, v01 = acc[mi][ni][1] + bv.y;
            float v10 = acc[mi][ni][2] + bv.x, v11 = acc[mi][ni][3] + bv.y;
            if (Cf) {
                float2 o0 = {v00, v01}, o1 = {v10, v11};
                *(float2*)(Cf + (size_t)row * ldC + col) = o0;
                *(float2*)(Cf + (size_t)(row + 8) * ldC + col) = o1;
            } else {
                *(__half2*)(Ch + (size_t)row * ldC + col) = __floats2half2_rn(v00, v01);
                *(__half2*)(Ch + (size_t)(row + 8) * ldC + col) = __floats2half2_rn(v10, v11);
            }
        }
    }
}

// ============ convert x -> fp16, fused g_block sigmoid ============
__global__ void __launch_bounds__(256) convx_kernel(const float* __restrict__ x,
    const float* __restrict__ wblk, const float* __restrict__ bblk)
{
    __shared__ __align__(16) float swt[8][512];   // wblk transposed
    int tid = threadIdx.x;
    for (int idx = tid; idx < 4096; idx += 256)
        swt[idx & 7][idx >> 3] = wblk[idx];
    __syncthreads();
    int wid = tid >> 5, lane = tid & 31;
    int row = blockIdx.x * 8 + wid;
    const float* xr = x + (size_t)row * 512;
    float acc[8] = {};
    #pragma unroll
    for (int i = 0; i < 4; i++) {
        int c = i * 128 + lane * 4;
        float4 v = *(const float4*)(xr + c);
        __half2 h0 = __floats2half2_rn(v.x, v.y);
        __half2 h1 = __floats2half2_rn(v.z, v.w);
        size_t o = (size_t)row * 512 + c;
        *(__half2*)(g_xq + o) = h0; *(__half2*)(g_xq + o + 2) = h1;
        #pragma unroll
        for (int h = 0; h < 8; h++) {
            float4 wv = *(const float4*)(&swt[h][c]);
            acc[h] += v.x * wv.x + v.y * wv.y + v.z * wv.z + v.w * wv.w;
        }
    }
    #pragma unroll
    for (int m = 16; m; m >>= 1)
        #pragma unroll
        for (int h = 0; h < 8; h++) acc[h] += __shfl_xor_sync(0xffffffffu, acc[h], m);
    if (lane == 0) {
        #pragma unroll
        for (int h = 0; h < 8; h++)
            g_gblock[row * 8 + h] = 1.f / (1.f + __expf(-(acc[h] + bblk[h])));
    }
}

// ============ weight transpose + fp16: W[K][N] -> T[N][K] ============
__global__ void wsplit_kernel(const float* __restrict__ W,
    __half* __restrict__ T, int Kd, int Nd)
{
    __shared__ float tile[32][33];
    int tx = threadIdx.x & 31, ty = threadIdx.x >> 5;
    int n0 = blockIdx.x * 32, k0 = blockIdx.y * 32;
    #pragma unroll
    for (int r = 0; r < 4; r++)
        tile[ty + r * 8][tx] = W[(size_t)(k0 + ty + r * 8) * Nd + n0 + tx];
    __syncthreads();
    #pragma unroll
    for (int r = 0; r < 4; r++) {
        int n = ty + r * 8;
        T[(size_t)(n0 + n) * Kd + k0 + tx] = __float2half_rn(tile[tx][n]);
    }
}

// ================= prep: fixed mask, bias diag, gate MLP =================
__global__ void prep_kernel(const int* __restrict__ mask,
                            const float* __restrict__ ef,
                            const float* __restrict__ w1, const float* __restrict__ b1,
                            const float* __restrict__ w2, const float* __restrict__ b2)
{
    __shared__ float sw1[64], sb1[16], sw2[128], sb2[8];
    __shared__ int ssum;
    int t   = threadIdx.x;          // k index
    int nbq = blockIdx.x;           // nb*64+q
    int q   = nbq & 63;
    sw1[t] = w1[t];
    sw2[t] = w2[t]; sw2[t + 64] = w2[t + 64];
    if (t < 16) sb1[t] = b1[t];
    if (t < 8)  sb2[t] = b2[t];
    if (t == 0) ssum = 0;
    __syncthreads();
    int m = mask[nbq * 64 + t];
    atomicAdd(&ssum, m);
    __syncthreads();
    int mf = m;
    if (q == t && ssum == 0) mf = 1;

    float e0, e1, e2, e3;
    if (q == t) { e0 = e1 = e2 = 0.f; e3 = 1.f; }
    else {
        const float* p = ef + ((size_t)nbq * 64 + t) * 4;
        e0 = p[0]; e1 = p[1]; e2 = p[2]; e3 = p[3];
    }
    float hb[16];
    #pragma unroll
    for (int i = 0; i < 16; i++) {
        float s = sb1[i] + e0 * sw1[i] + e1 * sw1[16 + i] + e2 * sw1[32 + i] + e3 * sw1[48 + i];
        hb[i] = 0.5f * s * (1.f + erff(s * 0.70710678118654752f));
    }
    #pragma unroll
    for (int h = 0; h < 8; h++) {
        float s = sb2[h];
        #pragma unroll
        for (int i = 0; i < 16; i++) s += hb[i] * sw2[i * 8 + h];
        g_gateh[h * NBLL + nbq * 64 + t] = __float2half_rn(mf ? s : 0.f);
    }
    g_smask[nbq * 64 + t] = e3 + (mf ? 0.f : -1e30f);
}

// ================= block mean =================
__global__ void bnode_kernel(const float* __restrict__ x)
{
    int bn = blockIdx.x, c = threadIdx.x;   // 512 threads
    const float* p = x + (size_t)bn * 64 * 512 + c;
    float s = 0.f;
    #pragma unroll 8
    for (int l = 0; l < 64; l++) s += p[l * 512];
    g_bnode[bn * 512 + c] = s * (1.f / 64.f);
}

// ================= v_block = bnode @ w_qkv[:,2C:] + b =================
__global__ void vblock_kernel(const float* __restrict__ wqkv, const float* __restrict__ bqkv)
{
    __shared__ float sA[16][512];
    int t = threadIdx.x;                 // 512
    int r0 = blockIdx.x * 16;
    for (int r = 0; r < 16; r++) sA[r][t] = g_bnode[(r0 + r) * 512 + t];
    __syncthreads();
    float acc[16];
    #pragma unroll
    for (int r = 0; r < 16; r++) acc[r] = 0.f;
    for (int k = 0; k < 512; k++) {
        float w = wqkv[(size_t)k * 1536 + 1024 + t];
        #pragma unroll
        for (int r = 0; r < 16; r++) acc[r] += sA[r][k] * w;
    }
    float bb = bqkv[1024 + t];
    #pragma unroll
    for (int r = 0; r < 16; r++) g_vblock[(r0 + r) * 512 + t] = acc[r] + bb;
}

// ================= attention per (b,nb,h): HMMA version =================
// 128 threads = 4 warps; warp w owns query rows 16w..16w+15.
// scores: q(A) x k(B) identical ldmatrix geometry to the GEMM (proven).
// P repacked from score C-frags into A-frags (flash-attn register reuse).
// V consumed via ldmatrix.x4.trans (B col-major for row.col mma).
__global__ void __launch_bounds__(128) attn_kernel()
{
    __shared__ __align__(128) __half qs[64 * 64];
    __shared__ __align__(128) __half ks_[64 * 64];
    __shared__ __align__(128) __half vs[64 * 64];
    int tid = threadIdx.x, warp = tid >> 5, lane = tid & 31;
    int cid = blockIdx.x;
    int h  = cid & 7;
    int bn = cid >> 3;
    int nb = bn & 511;
    int rbase = bn * 64;
    uint32_t sq = s2u(qs), sk = s2u(ks_), sv = s2u(vs);

    // load q,k,v fp16 tiles: 64 rows x 8 x 16B each
    #pragma unroll
    for (int r = 0; r < 4; r++) {
        int idx = r * 128 + tid;            // 0..511
        int row = idx >> 3, ch = idx & 7;
        uint32_t d = row * 128 + ((ch ^ (row & 7)) << 4);
        const __half* base = g_qkvh + (size_t)(rbase + row) * 1536 + h * 64 + ch * 8;
        cp16(sq + d, base);
        cp16(sk + d, base + 512);
        cp16(sv + d, base + 1024);
    }
    asm volatile("cp.async.commit_group;" ::: "memory");
    asm volatile("cp.async.wait_group 0;" ::: "memory");
    __syncthreads();

    int wq0 = warp * 16;
    int aRow = wq0 + (lane & 15);
    int aSel = lane >> 4;
    int bRowB = (lane & 7) + ((lane >> 4) << 3);
    int bSel = (lane >> 3) & 1;

    // ---- scores = q k^T (fp32 acc) ----
    float acc[8][4];
    #pragma unroll
    for (int t = 0; t < 8; t++)
        #pragma unroll
        for (int j = 0; j < 4; j++) acc[t][j] = 0.f;

    #pragma unroll
    for (int kk = 0; kk < 4; kk++) {
        uint32_t af[4];
        int chA = kk * 2 + aSel;
        LDSM4(af, sq + aRow * 128 + ((chA ^ (aRow & 7)) << 4));
        int chB = kk * 2 + bSel;
        #pragma unroll
        for (int nj = 0; nj < 4; nj++) {
            uint32_t bf[4];
            int bR = nj * 16 + bRowB;
            LDSM4(bf, sk + bR * 128 + ((chB ^ (bR & 7)) << 4));
            MMA16816H(acc[nj * 2 + 0], af, (bf + 0));
            MMA16816H(acc[nj * 2 + 1], af, (bf + 2));
        }
    }

    // ---- softmax on C-frags: rows wq0+r0 and wq0+r0+8 ----
    int r0 = lane >> 2, c0 = (lane & 3) * 2;
    int qr0 = wq0 + r0, qr1 = qr0 + 8;
    const float* smp = g_smask + nb * 4096;
    float mx0 = -1e30f, mx1 = -1e30f;
    #pragma unroll
    for (int t = 0; t < 8; t++) {
        int col = t * 8 + c0;
        float2 m0 = *(const float2*)(smp + qr0 * 64 + col);
        float2 m1 = *(const float2*)(smp + qr1 * 64 + col);
        acc[t][0] = acc[t][0] * 0.125f + m0.x;
        acc[t][1] = acc[t][1] * 0.125f + m0.y;
        acc[t][2] = acc[t][2] * 0.125f + m1.x;
        acc[t][3] = acc[t][3] * 0.125f + m1.y;
        mx0 = fmaxf(mx0, fmaxf(acc[t][0], acc[t][1]));
        mx1 = fmaxf(mx1, fmaxf(acc[t][2], acc[t][3]));
    }
    mx0 = fmaxf(mx0, __shfl_xor_sync(0xffffffffu, mx0, 1));
    mx0 = fmaxf(mx0, __shfl_xor_sync(0xffffffffu, mx0, 2));
    mx1 = fmaxf(mx1, __shfl_xor_sync(0xffffffffu, mx1, 1));
    mx1 = fmaxf(mx1, __shfl_xor_sync(0xffffffffu, mx1, 2));
    float s0 = 0.f, s1 = 0.f;
    #pragma unroll
    for (int t = 0; t < 8; t++) {
        acc[t][0] = __expf(acc[t][0] - mx0); s0 += acc[t][0];
        acc[t][1] = __expf(acc[t][1] - mx0); s0 += acc[t][1];
        acc[t][2] = __expf(acc[t][2] - mx1); s1 += acc[t][2];
        acc[t][3] = __expf(acc[t][3] - mx1); s1 += acc[t][3];
    }
    s0 += __shfl_xor_sync(0xffffffffu, s0, 1);
    s0 += __shfl_xor_sync(0xffffffffu, s0, 2);
    s1 += __shfl_xor_sync(0xffffffffu, s1, 1);
    s1 += __shfl_xor_sync(0xffffffffu, s1, 2);
    float inv0 = 1.f / s0, inv1 = 1.f / s1;

    // ---- combined = P + gate, packed as A-frags per k16 step ----
    const __half* gp = g_gateh + (size_t)h * NBLL + nb * 4096;
    uint32_t pa[4][4];
    #pragma unroll
    for (int t2 = 0; t2 < 4; t2++) {
        int colA = t2 * 16 + c0;
        float2 f00 = __half22float2(*(const __half2*)(gp + qr0 * 64 + colA));
        float2 f01 = __half22float2(*(const __half2*)(gp + qr0 * 64 + colA + 8));
        float2 f10 = __half22float2(*(const __half2*)(gp + qr1 * 64 + colA));
        float2 f11 = __half22float2(*(const __half2*)(gp + qr1 * 64 + colA + 8));
        __half2 a0 = __floats2half2_rn(acc[2*t2][0] * inv0 + f00.x, acc[2*t2][1] * inv0 + f00.y);
        __half2 a1 = __floats2half2_rn(acc[2*t2][2] * inv1 + f10.x, acc[2*t2][3] * inv1 + f10.y);
        __half2 a2 = __floats2half2_rn(acc[2*t2+1][0] * inv0 + f01.x, acc[2*t2+1][1] * inv0 + f01.y);
        __half2 a3 = __floats2half2_rn(acc[2*t2+1][2] * inv1 + f11.x, acc[2*t2+1][3] * inv1 + f11.y);
        pa[t2][0] = *(uint32_t*)&a0; pa[t2][1] = *(uint32_t*)&a1;
        pa[t2][2] = *(uint32_t*)&a2; pa[t2][3] = *(uint32_t*)&a3;
    }

    // ---- out = combined @ v (V via ldmatrix.trans) ----
    float oacc[8][4];
    #pragma unroll
    for (int t = 0; t < 8; t++)
        #pragma unroll
        for (int j = 0; j < 4; j++) oacc[t][j] = 0.f;

    int vRowB = lane & 15;          // within k16
    int vSel = lane >> 4;           // n-chunk select
    #pragma unroll
    for (int kv = 0; kv < 4; kv++) {
        int R = kv * 16 + vRowB;
        #pragma unroll
        for (int nj = 0; nj < 4; nj++) {
            uint32_t bf[4];
            int ch = nj * 2 + vSel;
            LDSM4T(bf, sv + R * 128 + ((ch ^ (R & 7)) << 4));
            MMA16816H(oacc[nj * 2 + 0], pa[kv], (bf + 0));
            MMA16816H(oacc[nj * 2 + 1], pa[kv], (bf + 2));
        }
    }

    // ---- + g_block * v_block, store fp16 ----
    int orow0 = rbase + qr0, orow1 = rbase + qr1;
    float gb0 = g_gblock[orow0 * 8 + h], gb1 = g_gblock[orow1 * 8 + h];
    const float* vbp = g_vblock + bn * 512 + h * 64;
    #pragma unroll
    for (int t = 0; t < 8; t++) {
        int col = t * 8 + c0;
        float2 vb = *(const float2*)(vbp + col);
        __half2 o0 = __floats2half2_rn(oacc[t][0] + gb0 * vb.x, oacc[t][1] + gb0 * vb.y);
        __half2 o1 = __floats2half2_rn(oacc[t][2] + gb1 * vb.x, oacc[t][3] + gb1 * vb.y);
        *(__half2*)(g_mq + (size_t)orow0 * 512 + h * 64 + col) = o0;
        *(__half2*)(g_mq + (size_t)orow1 * 512 + h * 64 + col) = o1;
    }
}

// ================= launch =================
extern "C" void kernel_launch(void* const* d_in, const int* in_sizes, int n_in,
                              void* d_out, int out_size)
{
    const float* x       = (const float*)d_in[0];
    const int*   amask   = (const int*)  d_in[1];
    const float* edge    = (const float*)d_in[2];
    const float* w_qkv   = (const float*)d_in[3];
    const float* b_qkv   = (const float*)d_in[4];
    const float* w_proj  = (const float*)d_in[5];
    const float* b_proj  = (const float*)d_in[6];
    const float* w_eg1   = (const float*)d_in[7];
    const float* b_eg1   = (const float*)d_in[8];
    const float* w_eg2   = (const float*)d_in[9];
    const float* b_eg2   = (const float*)d_in[10];
    const float* w_blk   = (const float*)d_in[11];
    const float* b_blk   = (const float*)d_in[12];
    float* out = (float*)d_out;

    void *qkvh, *xq, *mq, *wq, *wp;
    cudaGetSymbolAddress(&qkvh, g_qkvh);
    cudaGetSymbolAddress(&xq, g_xq);
    cudaGetSymbolAddress(&mq, g_mq);
    cudaGetSymbolAddress(&wq, g_wq);
    cudaGetSymbolAddress(&wp, g_wp);

    cudaFuncSetAttribute(gemm_fp16_kernel,
                         cudaFuncAttributeMaxDynamicSharedMemorySize, GSMEM);

    convx_kernel<<<MROWS / 8, 256>>>(x, w_blk, b_blk);
    wsplit_kernel<<<dim3(48, 16), 256>>>(w_qkv, (__half*)wq, 512, 1536);
    wsplit_kernel<<<dim3(16, 16), 256>>>(w_proj, (__half*)wp, 512, 512);
    prep_kernel  <<<NB_ * 64, 64>>>(amask, edge, w_eg1, b_eg1, w_eg2, b_eg2);
    bnode_kernel <<<BNB, 512>>>(x);
    vblock_kernel<<<64, 512>>>(w_qkv, b_qkv);

    gemm_fp16_kernel<<<dim3(6, 512), 512, GSMEM>>>(
        (const __half*)xq, (const __half*)wq, b_qkv,
        nullptr, (__half*)qkvh, 1536);

    attn_kernel<<<BNB * H_, 128>>>();

    gemm_fp16_kernel<<<dim3(2, 512), 512, GSMEM>>>(
        (const __half*)mq, (const __half*)wp, b_proj,
        out, nullptr, 512);
}

// round 16
// speedup vs baseline: 1.3471x; 1.0246x over previous
#include <cuda_runtime.h>
#include <cuda_bf16.h>
#include <cuda_fp16.h>
#include <math.h>
#include <stdint.h>

#define B_    2
#define NB_   512
#define L_    64
#define H_    8
#define DH_   64
#define C_    512
#define C3_   1536
#define MROWS 65536          // B*NB*L
#define BNB   1024           // B*NB
#define NBLL  2097152        // NB*L*L

// ---------------- static scratch (no allocations allowed) ----------------
__device__ __half g_qkvh [100663296]; // [MROWS][1536] fp16
__device__ __half g_gateh[16777216];   // [H][NB][L][L] fp16
__device__ float g_smask [2097152];    // [NB][L][L]   bias3 + (mask?0:-1e30)
__device__ float g_gblock[524288];     // [MROWS][H]
__device__ float g_vblock[524288];     // [BNB][512]
__device__ float g_bnode [524288];     // [BNB][512]
__device__ __half g_xq[33554432];      // x fp16 [MROWS][512]
__device__ __half g_mq[33554432];      // xmid fp16
__device__ __half g_wq[786432];        // w_qkv^T fp16 [1536][512]
__device__ __half g_wp[262144];        // w_proj^T fp16 [512][512]

// =================== PTX helpers (baseline ISA only: sm_80+) ===================
__device__ __forceinline__ uint32_t s2u(const void* p) {
    return (uint32_t)__cvta_generic_to_shared(p);
}
__device__ __forceinline__ void cp16(uint32_t dst, const void* src) {
    asm volatile("cp.async.cg.shared.global [%0], [%1], 16;" :: "r"(dst), "l"(src));
}
#define LDSM4(r, a) \
    asm volatile("ldmatrix.sync.aligned.m8n8.x4.shared.b16 {%0,%1,%2,%3}, [%4];" \
        : "=r"((r)[0]), "=r"((r)[1]), "=r"((r)[2]), "=r"((r)[3]) : "r"(a))
#define LDSM4T(r, a) \
    asm volatile("ldmatrix.sync.aligned.m8n8.x4.trans.shared.b16 {%0,%1,%2,%3}, [%4];" \
        : "=r"((r)[0]), "=r"((r)[1]), "=r"((r)[2]), "=r"((r)[3]) : "r"(a))
#define MMA16816H(c, a, b) \
    asm volatile("mma.sync.aligned.m16n8k16.row.col.f32.f16.f16.f32 " \
        "{%0,%1,%2,%3}, {%4,%5,%6,%7}, {%8,%9}, {%0,%1,%2,%3};" \
        : "+f"((c)[0]), "+f"((c)[1]), "+f"((c)[2]), "+f"((c)[3]) \
        : "r"((a)[0]), "r"((a)[1]), "r"((a)[2]), "r"((a)[3]), "r"((b)[0]), "r"((b)[1]))

// =================== fp16 single-pass GEMM via HMMA mma.sync ===================
// CTA 128(M) x 256(N), 512 threads (16 warps 4Mx4N), warp tile 32x64.
// K chunks of 64, FOUR-stage cp.async pipeline, one __syncthreads per chunk.
#define A_TILE 16384
#define B_TILE 32768
#define STAGE_BYTES 49152
#define GSMEM (4 * STAGE_BYTES)

__device__ __forceinline__ void gemm_load_stage(
    uint32_t st, int tid, int kc,
    const __half* __restrict__ A, const __half* __restrict__ Bm)
{
    #pragma unroll
    for (int r = 0; r < 2; r++) {
        int idx = r * 512 + tid;
        int row = idx >> 3, ch = idx & 7;
        uint32_t d = row * 128 + ((ch ^ (row & 7)) << 4);
        cp16(st + d, A + (size_t)row * 512 + kc * 64 + ch * 8);
    }
    #pragma unroll
    for (int r = 0; r < 4; r++) {
        int idx = r * 512 + tid;
        int row = idx >> 3, ch = idx & 7;
        uint32_t d = row * 128 + ((ch ^ (row & 7)) << 4);
        cp16(st + A_TILE + d, Bm + (size_t)row * 512 + kc * 64 + ch * 8);
    }
    asm volatile("cp.async.commit_group;" ::: "memory");
}

__global__ void __launch_bounds__(512, 1)
gemm_fp16_kernel(const __half* __restrict__ A, const __half* __restrict__ Bm,
                 const float* __restrict__ bias, float* __restrict__ Cf,
                 __half* __restrict__ Ch, int ldC)
{
    extern __shared__ __align__(1024) char smem[];
    uint32_t sb = s2u(smem);
    int tid = threadIdx.x;
    int warp = tid >> 5, lane = tid & 31;
    int m0 = blockIdx.y * 128, n0 = blockIdx.x * 256;
    int wm = (warp & 3) * 32, wn = (warp >> 2) * 64;

    const __half* pA = A + (size_t)m0 * 512;
    const __half* pB = Bm + (size_t)n0 * 512;

    float acc[2][8][4];
    #pragma unroll
    for (int i = 0; i < 2; i++)
        #pragma unroll
        for (int j = 0; j < 8; j++)
            #pragma unroll
            for (int t = 0; t < 4; t++) acc[i][j][t] = 0.f;

    int aRow[2], bRow[4];
    #pragma unroll
    for (int mi = 0; mi < 2; mi++) aRow[mi] = wm + mi * 16 + (lane & 15);
    #pragma unroll
    for (int nj = 0; nj < 4; nj++) bRow[nj] = wn + nj * 16 + (lane & 7) + ((lane >> 4) << 3);
    int aSel = lane >> 4;
    int bSel = (lane >> 3) & 1;

    gemm_load_stage(sb + 0 * STAGE_BYTES, tid, 0, pA, pB);
    gemm_load_stage(sb + 1 * STAGE_BYTES, tid, 1, pA, pB);
    gemm_load_stage(sb + 2 * STAGE_BYTES, tid, 2, pA, pB);

    for (int kc = 0; kc < 8; kc++) {
        // guarantee stage kc complete (pending = newest 2 at steady state)
        if (kc < 6)       asm volatile("cp.async.wait_group 2;" ::: "memory");
        else if (kc == 6) asm volatile("cp.async.wait_group 1;" ::: "memory");
        else              asm volatile("cp.async.wait_group 0;" ::: "memory");
        __syncthreads();   // all warps done consuming stage kc-1 -> safe to overwrite

        if (kc + 3 < 8)
            gemm_load_stage(sb + ((kc + 3) & 3) * STAGE_BYTES, tid, kc + 3, pA, pB);

        uint32_t stA = sb + (kc & 3) * STAGE_BYTES;
        uint32_t stB = stA + A_TILE;

        #pragma unroll
        for (int kk = 0; kk < 4; kk++) {
            uint32_t af[2][4];
            int chA = kk * 2 + aSel;
            #pragma unroll
            for (int mi = 0; mi < 2; mi++) {
                uint32_t ad = aRow[mi] * 128 + ((chA ^ (aRow[mi] & 7)) << 4);
                LDSM4(af[mi], stA + ad);
            }
            int chB = kk * 2 + bSel;
            #pragma unroll
            for (int nj = 0; nj < 4; nj++) {
                uint32_t bf[4];
                uint32_t bd = bRow[nj] * 128 + ((chB ^ (bRow[nj] & 7)) << 4);
                LDSM4(bf, stB + bd);
                #pragma unroll
                for (int mi = 0; mi < 2; mi++) {
                    MMA16816H(acc[mi][nj * 2 + 0], af[mi], (bf + 0));
                    MMA16816H(acc[mi][nj * 2 + 1], af[mi], (bf + 2));
                }
            }
        }
    }

    // epilogue: +bias; fp32 or fp16 store
    #pragma unroll
    for (int mi = 0; mi < 2; mi++) {
        int row = m0 + wm + mi * 16 + (lane >> 2);
        #pragma unroll
        for (int ni = 0; ni < 8; ni++) {
            int col = n0 + wn + ni * 8 + (lane & 3) * 2;
            float2 bv = *(const float2*)(bias + col);
            float v00 = acc[mi][ni][0] + bv.x, v01 = acc[mi][ni][1] + bv.y;
            float v10 = acc[mi][ni][2] + bv.x, v11 = acc[mi][ni][3] + bv.y;
            if (Cf) {
                float2 o0 = {v00, v01}, o1 = {v10, v11};
                *(float2*)(Cf + (size_t)row * ldC + col) = o0;
                *(float2*)(Cf + (size_t)(row + 8) * ldC + col) = o1;
            } else {
                *(__half2*)(Ch + (size_t)row * ldC + col) = __floats2half2_rn(v00, v01);
                *(__half2*)(Ch + (size_t)(row + 8) * ldC + col) = __floats2half2_rn(v10, v11);
            }
        }
    }
}

// ============ convert x -> fp16, fused g_block sigmoid ============
__global__ void __launch_bounds__(256) convx_kernel(const float* __restrict__ x,
    const float* __restrict__ wblk, const float* __restrict__ bblk)
{
    __shared__ __align__(16) float swt[8][512];   // wblk transposed
    int tid = threadIdx.x;
    for (int idx = tid; idx < 4096; idx += 256)
        swt[idx & 7][idx >> 3] = wblk[idx];
    __syncthreads();
    int wid = tid >> 5, lane = tid & 31;
    int row = blockIdx.x * 8 + wid;
    const float* xr = x + (size_t)row * 512;
    float acc[8] = {};
    #pragma unroll
    for (int i = 0; i < 4; i++) {
        int c = i * 128 + lane * 4;
        float4 v = *(const float4*)(xr + c);
        __half2 h0 = __floats2half2_rn(v.x, v.y);
        __half2 h1 = __floats2half2_rn(v.z, v.w);
        size_t o = (size_t)row * 512 + c;
        *(__half2*)(g_xq + o) = h0; *(__half2*)(g_xq + o + 2) = h1;
        #pragma unroll
        for (int h = 0; h < 8; h++) {
            float4 wv = *(const float4*)(&swt[h][c]);
            acc[h] += v.x * wv.x + v.y * wv.y + v.z * wv.z + v.w * wv.w;
        }
    }
    #pragma unroll
    for (int m = 16; m; m >>= 1)
        #pragma unroll
        for (int h = 0; h < 8; h++) acc[h] += __shfl_xor_sync(0xffffffffu, acc[h], m);
    if (lane == 0) {
        #pragma unroll
        for (int h = 0; h < 8; h++)
            g_gblock[row * 8 + h] = 1.f / (1.f + __expf(-(acc[h] + bblk[h])));
    }
}

// ============ weight transpose + fp16: W[K][N] -> T[N][K] ============
__global__ void wsplit_kernel(const float* __restrict__ W,
    __half* __restrict__ T, int Kd, int Nd)
{
    __shared__ float tile[32][33];
    int tx = threadIdx.x & 31, ty = threadIdx.x >> 5;
    int n0 = blockIdx.x * 32, k0 = blockIdx.y * 32;
    #pragma unroll
    for (int r = 0; r < 4; r++)
        tile[ty + r * 8][tx] = W[(size_t)(k0 + ty + r * 8) * Nd + n0 + tx];
    __syncthreads();
    #pragma unroll
    for (int r = 0; r < 4; r++) {
        int n = ty + r * 8;
        T[(size_t)(n0 + n) * Kd + k0 + tx] = __float2half_rn(tile[tx][n]);
    }
}

// ================= prep: fixed mask, bias diag, gate MLP =================
// gelu via tanh form: for |h| <= ~0.2 here, identical to erf form to < 1e-6.
__global__ void prep_kernel(const int* __restrict__ mask,
                            const float* __restrict__ ef,
                            const float* __restrict__ w1, const float* __restrict__ b1,
                            const float* __restrict__ w2, const float* __restrict__ b2)
{
    __shared__ float sw1[64], sb1[16], sw2[128], sb2[8];
    __shared__ int ssum;
    int t   = threadIdx.x;          // k index
    int nbq = blockIdx.x;           // nb*64+q
    int q   = nbq & 63;
    sw1[t] = w1[t];
    sw2[t] = w2[t]; sw2[t + 64] = w2[t + 64];
    if (t < 16) sb1[t] = b1[t];
    if (t < 8)  sb2[t] = b2[t];
    if (t == 0) ssum = 0;
    __syncthreads();
    int m = mask[nbq * 64 + t];
    atomicAdd(&ssum, m);
    __syncthreads();
    int mf = m;
    if (q == t && ssum == 0) mf = 1;

    float e0, e1, e2, e3;
    if (q == t) { e0 = e1 = e2 = 0.f; e3 = 1.f; }
    else {
        const float* p = ef + ((size_t)nbq * 64 + t) * 4;
        e0 = p[0]; e1 = p[1]; e2 = p[2]; e3 = p[3];
    }
    float hb[16];
    #pragma unroll
    for (int i = 0; i < 16; i++) {
        float s = sb1[i] + e0 * sw1[i] + e1 * sw1[16 + i] + e2 * sw1[32 + i] + e3 * sw1[48 + i];
        float u = 1.5957691216f * s * (1.f + 0.044715f * s * s); // 2*0.79788456*(...)
        float e = __expf(u);
        float th = (e - 1.f) * __fdividef(1.f, e + 1.f);         // tanh
        hb[i] = 0.5f * s * (1.f + th);
    }
    #pragma unroll
    for (int h = 0; h < 8; h++) {
        float s = sb2[h];
        #pragma unroll
        for (int i = 0; i < 16; i++) s += hb[i] * sw2[i * 8 + h];
        g_gateh[h * NBLL + nbq * 64 + t] = __float2half_rn(mf ? s : 0.f);
    }
    g_smask[nbq * 64 + t] = e3 + (mf ? 0.f : -1e30f);
}

// ================= block mean =================
__global__ void bnode_kernel(const float* __restrict__ x)
{
    int bn = blockIdx.x, c = threadIdx.x;   // 512 threads
    const float* p = x + (size_t)bn * 64 * 512 + c;
    float s = 0.f;
    #pragma unroll 8
    for (int l = 0; l < 64; l++) s += p[l * 512];
    g_bnode[bn * 512 + c] = s * (1.f / 64.f);
}

// ================= v_block = bnode @ w_qkv[:,2C:] + b =================
__global__ void vblock_kernel(const float* __restrict__ wqkv, const float* __restrict__ bqkv)
{
    __shared__ float sA[16][512];
    int t = threadIdx.x;                 // 512
    int r0 = blockIdx.x * 16;
    for (int r = 0; r < 16; r++) sA[r][t] = g_bnode[(r0 + r) * 512 + t];
    __syncthreads();
    float acc[16];
    #pragma unroll
    for (int r = 0; r < 16; r++) acc[r] = 0.f;
    for (int k = 0; k < 512; k++) {
        float w = wqkv[(size_t)k * 1536 + 1024 + t];
        #pragma unroll
        for (int r = 0; r < 16; r++) acc[r] += sA[r][k] * w;
    }
    float bb = bqkv[1024 + t];
    #pragma unroll
    for (int r = 0; r < 16; r++) g_vblock[(r0 + r) * 512 + t] = acc[r] + bb;
}

// ================= attention per (b,nb,h): HMMA =================
__global__ void __launch_bounds__(128) attn_kernel()
{
    __shared__ __align__(128) __half qs[64 * 64];
    __shared__ __align__(128) __half ks_[64 * 64];
    __shared__ __align__(128) __half vs[64 * 64];
    int tid = threadIdx.x, warp = tid >> 5, lane = tid & 31;
    int cid = blockIdx.x;
    int h  = cid & 7;
    int bn = cid >> 3;
    int nb = bn & 511;
    int rbase = bn * 64;
    uint32_t sq = s2u(qs), sk = s2u(ks_), sv = s2u(vs);

    #pragma unroll
    for (int r = 0; r < 4; r++) {
        int idx = r * 128 + tid;            // 0..511
        int row = idx >> 3, ch = idx & 7;
        uint32_t d = row * 128 + ((ch ^ (row & 7)) << 4);
        const __half* base = g_qkvh + (size_t)(rbase + row) * 1536 + h * 64 + ch * 8;
        cp16(sq + d, base);
        cp16(sk + d, base + 512);
        cp16(sv + d, base + 1024);
    }
    asm volatile("cp.async.commit_group;" ::: "memory");
    asm volatile("cp.async.wait_group 0;" ::: "memory");
    __syncthreads();

    int wq0 = warp * 16;
    int aRow = wq0 + (lane & 15);
    int aSel = lane >> 4;
    int bRowB = (lane & 7) + ((lane >> 4) << 3);
    int bSel = (lane >> 3) & 1;

    float acc[8][4];
    #pragma unroll
    for (int t = 0; t < 8; t++)
        #pragma unroll
        for (int j = 0; j < 4; j++) acc[t][j] = 0.f;

    #pragma unroll
    for (int kk = 0; kk < 4; kk++) {
        uint32_t af[4];
        int chA = kk * 2 + aSel;
        LDSM4(af, sq + aRow * 128 + ((chA ^ (aRow & 7)) << 4));
        int chB = kk * 2 + bSel;
        #pragma unroll
        for (int nj = 0; nj < 4; nj++) {
            uint32_t bf[4];
            int bR = nj * 16 + bRowB;
            LDSM4(bf, sk + bR * 128 + ((chB ^ (bR & 7)) << 4));
            MMA16816H(acc[nj * 2 + 0], af, (bf + 0));
            MMA16816H(acc[nj * 2 + 1], af, (bf + 2));
        }
    }

    int r0 = lane >> 2, c0 = (lane & 3) * 2;
    int qr0 = wq0 + r0, qr1 = qr0 + 8;
    const float* smp = g_smask + nb * 4096;
    float mx0 = -1e30f, mx1 = -1e30f;
    #pragma unroll
    for (int t = 0; t < 8; t++) {
        int col = t * 8 + c0;
        float2 m0 = *(const float2*)(smp + qr0 * 64 + col);
        float2 m1 = *(const float2*)(smp + qr1 * 64 + col);
        acc[t][0] = acc[t][0] * 0.125f + m0.x;
        acc[t][1] = acc[t][1] * 0.125f + m0.y;
        acc[t][2] = acc[t][2] * 0.125f + m1.x;
        acc[t][3] = acc[t][3] * 0.125f + m1.y;
        mx0 = fmaxf(mx0, fmaxf(acc[t][0], acc[t][1]));
        mx1 = fmaxf(mx1, fmaxf(acc[t][2], acc[t][3]));
    }
    mx0 = fmaxf(mx0, __shfl_xor_sync(0xffffffffu, mx0, 1));
    mx0 = fmaxf(mx0, __shfl_xor_sync(0xffffffffu, mx0, 2));
    mx1 = fmaxf(mx1, __shfl_xor_sync(0xffffffffu, mx1, 1));
    mx1 = fmaxf(mx1, __shfl_xor_sync(0xffffffffu, mx1, 2));
    float s0 = 0.f, s1 = 0.f;
    #pragma unroll
    for (int t = 0; t < 8; t++) {
        acc[t][0] = __expf(acc[t][0] - mx0); s0 += acc[t][0];
        acc[t][1] = __expf(acc[t][1] - mx0); s0 += acc[t][1];
        acc[t][2] = __expf(acc[t][2] - mx1); s1 += acc[t][2];
        acc[t][3] = __expf(acc[t][3] - mx1); s1 += acc[t][3];
    }
    s0 += __shfl_xor_sync(0xffffffffu, s0, 1);
    s0 += __shfl_xor_sync(0xffffffffu, s0, 2);
    s1 += __shfl_xor_sync(0xffffffffu, s1, 1);
    s1 += __shfl_xor_sync(0xffffffffu, s1, 2);
    float inv0 = 1.f / s0, inv1 = 1.f / s1;

    const __half* gp = g_gateh + (size_t)h * NBLL + nb * 4096;
    uint32_t pa[4][4];
    #pragma unroll
    for (int t2 = 0; t2 < 4; t2++) {
        int colA = t2 * 16 + c0;
        float2 f00 = __half22float2(*(const __half2*)(gp + qr0 * 64 + colA));
        float2 f01 = __half22float2(*(const __half2*)(gp + qr0 * 64 + colA + 8));
        float2 f10 = __half22float2(*(const __half2*)(gp + qr1 * 64 + colA));
        float2 f11 = __half22float2(*(const __half2*)(gp + qr1 * 64 + colA + 8));
        __half2 a0 = __floats2half2_rn(acc[2*t2][0] * inv0 + f00.x, acc[2*t2][1] * inv0 + f00.y);
        __half2 a1 = __floats2half2_rn(acc[2*t2][2] * inv1 + f10.x, acc[2*t2][3] * inv1 + f10.y);
        __half2 a2 = __floats2half2_rn(acc[2*t2+1][0] * inv0 + f01.x, acc[2*t2+1][1] * inv0 + f01.y);
        __half2 a3 = __floats2half2_rn(acc[2*t2+1][2] * inv1 + f11.x, acc[2*t2+1][3] * inv1 + f11.y);
        pa[t2][0] = *(uint32_t*)&a0; pa[t2][1] = *(uint32_t*)&a1;
        pa[t2][2] = *(uint32_t*)&a2; pa[t2][3] = *(uint32_t*)&a3;
    }

    float oacc[8][4];
    #pragma unroll
    for (int t = 0; t < 8; t++)
        #pragma unroll
        for (int j = 0; j < 4; j++) oacc[t][j] = 0.f;

    int vRowB = lane & 15;
    int vSel = lane >> 4;
    #pragma unroll
    for (int kv = 0; kv < 4; kv++) {
        int R = kv * 16 + vRowB;
        #pragma unroll
        for (int nj = 0; nj < 4; nj++) {
            uint32_t bf[4];
            int ch = nj * 2 + vSel;
            LDSM4T(bf, sv + R * 128 + ((ch ^ (R & 7)) << 4));
            MMA16816H(oacc[nj * 2 + 0], pa[kv], (bf + 0));
            MMA16816H(oacc[nj * 2 + 1], pa[kv], (bf + 2));
        }
    }

    int orow0 = rbase + qr0, orow1 = rbase + qr1;
    float gb0 = g_gblock[orow0 * 8 + h], gb1 = g_gblock[orow1 * 8 + h];
    const float* vbp = g_vblock + bn * 512 + h * 64;
    #pragma unroll
    for (int t = 0; t < 8; t++) {
        int col = t * 8 + c0;
        float2 vb = *(const float2*)(vbp + col);
        __half2 o0 = __floats2half2_rn(oacc[t][0] + gb0 * vb.x, oacc[t][1] + gb0 * vb.y);
        __half2 o1 = __floats2half2_rn(oacc[t][2] + gb1 * vb.x, oacc[t][3] + gb1 * vb.y);
        *(__half2*)(g_mq + (size_t)orow0 * 512 + h * 64 + col) = o0;
        *(__half2*)(g_mq + (size_t)orow1 * 512 + h * 64 + col) = o1;
    }
}

// ================= launch =================
extern "C" void kernel_launch(void* const* d_in, const int* in_sizes, int n_in,
                              void* d_out, int out_size)
{
    const float* x       = (const float*)d_in[0];
    const int*   amask   = (const int*)  d_in[1];
    const float* edge    = (const float*)d_in[2];
    const float* w_qkv   = (const float*)d_in[3];
    const float* b_qkv   = (const float*)d_in[4];
    const float* w_proj  = (const float*)d_in[5];
    const float* b_proj  = (const float*)d_in[6];
    const float* w_eg1   = (const float*)d_in[7];
    const float* b_eg1   = (const float*)d_in[8];
    const float* w_eg2   = (const float*)d_in[9];
    const float* b_eg2   = (const float*)d_in[10];
    const float* w_blk   = (const float*)d_in[11];
    const float* b_blk   = (const float*)d_in[12];
    float* out = (float*)d_out;

    void *qkvh, *xq, *mq, *wq, *wp;
    cudaGetSymbolAddress(&qkvh, g_qkvh);
    cudaGetSymbolAddress(&xq, g_xq);
    cudaGetSymbolAddress(&mq, g_mq);
    cudaGetSymbolAddress(&wq, g_wq);
    cudaGetSymbolAddress(&wp, g_wp);

    cudaFuncSetAttribute(gemm_fp16_kernel,
                         cudaFuncAttributeMaxDynamicSharedMemorySize, GSMEM);

    convx_kernel<<<MROWS / 8, 256>>>(x, w_blk, b_blk);
    wsplit_kernel<<<dim3(48, 16), 256>>>(w_qkv, (__half*)wq, 512, 1536);
    wsplit_kernel<<<dim3(16, 16), 256>>>(w_proj, (__half*)wp, 512, 512);
    prep_kernel  <<<NB_ * 64, 64>>>(amask, edge, w_eg1, b_eg1, w_eg2, b_eg2);
    bnode_kernel <<<BNB, 512>>>(x);
    vblock_kernel<<<64, 512>>>(w_qkv, b_qkv);

    gemm_fp16_kernel<<<dim3(6, 512), 512, GSMEM>>>(
        (const __half*)xq, (const __half*)wq, b_qkv,
        nullptr, (__half*)qkvh, 1536);

    attn_kernel<<<BNB * H_, 128>>>();

    gemm_fp16_kernel<<<dim3(2, 512), 512, GSMEM>>>(
        (const __half*)mq, (const __half*)wp, b_proj,
        out, nullptr, 512);
}